// round 5
// baseline (speedup 1.0000x reference)
#include <cuda_runtime.h>
#include <cuda_bf16.h>
#include <math.h>
#include <stdint.h>

#define S_LEN  2048
#define DMODEL 4096
#define NHEADS 32
#define NKVH   8
#define HDIM   128
#define DFFN   16384

// ================= low-level helpers (base sm_103 ISA: ldmatrix/mma/cp.async) =================
__device__ __forceinline__ uint32_t smem_u32(const void* p) {
    uint32_t a;
    asm("{ .reg .u64 t; cvta.to.shared.u64 t, %1; cvt.u32.u64 %0, t; }" : "=r"(a) : "l"(p));
    return a;
}
__device__ __forceinline__ void cp_async16(uint32_t dst, const void* src) {
    asm volatile("cp.async.cg.shared.global [%0], [%1], 16;" :: "r"(dst), "l"(src));
}
#define CP_COMMIT() asm volatile("cp.async.commit_group;" ::: "memory")
#define CP_WAIT1()  asm volatile("cp.async.wait_group 1;" ::: "memory")

__device__ __forceinline__ void ldsm4(uint32_t* r, uint32_t addr) {
    asm volatile("ldmatrix.sync.aligned.m8n8.x4.shared.b16 {%0,%1,%2,%3}, [%4];"
        : "=r"(r[0]), "=r"(r[1]), "=r"(r[2]), "=r"(r[3]) : "r"(addr));
}
__device__ __forceinline__ void ldsm4t(uint32_t* r, uint32_t addr) {
    asm volatile("ldmatrix.sync.aligned.m8n8.x4.trans.shared.b16 {%0,%1,%2,%3}, [%4];"
        : "=r"(r[0]), "=r"(r[1]), "=r"(r[2]), "=r"(r[3]) : "r"(addr));
}
__device__ __forceinline__ void mma16816(float* d, const uint32_t* a, uint32_t b0, uint32_t b1) {
    asm volatile("mma.sync.aligned.m16n8k16.row.col.f32.bf16.bf16.f32 "
        "{%0,%1,%2,%3}, {%4,%5,%6,%7}, {%8,%9}, {%0,%1,%2,%3};"
        : "+f"(d[0]), "+f"(d[1]), "+f"(d[2]), "+f"(d[3])
        : "r"(a[0]), "r"(a[1]), "r"(a[2]), "r"(a[3]), "r"(b0), "r"(b1));
}

__device__ __forceinline__ uint32_t packbf(float a, float b) {
    return (uint32_t)__bfloat16_as_ushort(__float2bfloat16(a)) |
           ((uint32_t)__bfloat16_as_ushort(__float2bfloat16(b)) << 16);
}
__device__ __forceinline__ void split2(float a, float b, uint32_t& hi, uint32_t& lo) {
    __nv_bfloat16 ha = __float2bfloat16(a), hb = __float2bfloat16(b);
    hi = (uint32_t)__bfloat16_as_ushort(ha) | ((uint32_t)__bfloat16_as_ushort(hb) << 16);
    lo = packbf(a - __bfloat162float(ha), b - __bfloat162float(hb));
}

// ================= scratch (device globals; no allocation allowed) =================
__device__ float g_q   [S_LEN * DMODEL];
__device__ float g_k   [S_LEN * NKVH * HDIM];
__device__ float g_h   [S_LEN * DMODEL];
__device__ float g_gate[S_LEN * DFFN];

// bf16 hi/lo transposed weights: W^T [N, K]
__device__ __nv_bfloat16 g_wqT_h[DMODEL * DMODEL],        g_wqT_l[DMODEL * DMODEL];
__device__ __nv_bfloat16 g_wkT_h[NKVH * HDIM * DMODEL],   g_wkT_l[NKVH * HDIM * DMODEL];
__device__ __nv_bfloat16 g_wvT_h[NKVH * HDIM * DMODEL],   g_wvT_l[NKVH * HDIM * DMODEL];
__device__ __nv_bfloat16 g_woT_h[DMODEL * DMODEL],        g_woT_l[DMODEL * DMODEL];
__device__ __nv_bfloat16 g_gwT_h[DFFN * DMODEL],          g_gwT_l[DFFN * DMODEL];
__device__ __nv_bfloat16 g_uwT_h[DFFN * DMODEL],          g_uwT_l[DFFN * DMODEL];
__device__ __nv_bfloat16 g_dwT_h[DMODEL * DFFN],          g_dwT_l[DMODEL * DFFN];

// bf16 hi/lo activations
__device__ __nv_bfloat16 g_xn_h [S_LEN * DMODEL],       g_xn_l [S_LEN * DMODEL];
__device__ __nv_bfloat16 g_qh  [S_LEN * DMODEL],        g_ql  [S_LEN * DMODEL];
__device__ __nv_bfloat16 g_kh  [S_LEN * NKVH * HDIM],   g_kl  [S_LEN * NKVH * HDIM];
__device__ __nv_bfloat16 g_vh  [S_LEN * NKVH * HDIM],   g_vl  [S_LEN * NKVH * HDIM];
__device__ __nv_bfloat16 g_at_h[S_LEN * DMODEL],        g_at_l[S_LEN * DMODEL];
__device__ __nv_bfloat16 g_x2_h[S_LEN * DMODEL],        g_x2_l[S_LEN * DMODEL];
__device__ __nv_bfloat16 g_ga_h[S_LEN * DFFN],          g_ga_l[S_LEN * DFFN];

// ================= RMSNorm -> bf16 hi/lo =================
__global__ __launch_bounds__(256) void rmsnorm_split_kernel(
    const float* __restrict__ x, const float* __restrict__ w,
    __nv_bfloat16* __restrict__ yh, __nv_bfloat16* __restrict__ yl)
{
    int row = blockIdx.x;
    const float* xr = x + (size_t)row * DMODEL;

    float4 vals[4];
    float ss = 0.f;
#pragma unroll
    for (int it = 0; it < 4; it++) {
        int idx = (threadIdx.x + it * 256) * 4;
        float4 v = *(const float4*)(xr + idx);
        vals[it] = v;
        ss += v.x*v.x + v.y*v.y + v.z*v.z + v.w*v.w;
    }
#pragma unroll
    for (int o = 16; o; o >>= 1) ss += __shfl_xor_sync(0xffffffffu, ss, o);

    __shared__ float red[8];
    if ((threadIdx.x & 31) == 0) red[threadIdx.x >> 5] = ss;
    __syncthreads();
    float tot = 0.f;
#pragma unroll
    for (int i = 0; i < 8; i++) tot += red[i];
    float inv = rsqrtf(tot * (1.f / DMODEL) + 1e-5f);

#pragma unroll
    for (int it = 0; it < 4; it++) {
        int idx = (threadIdx.x + it * 256) * 4;
        float4 v  = vals[it];
        float4 wv = *(const float4*)(w + idx);
        float r0 = v.x * inv * wv.x, r1 = v.y * inv * wv.y;
        float r2 = v.z * inv * wv.z, r3 = v.w * inv * wv.w;
        uint2 hv, lv;
        split2(r0, r1, hv.x, lv.x);
        split2(r2, r3, hv.y, lv.y);
        *(uint2*)(yh + (size_t)row * DMODEL + idx) = hv;
        *(uint2*)(yl + (size_t)row * DMODEL + idx) = lv;
    }
}

// ================= RoPE + L2-norm -> bf16 hi/lo =================
__global__ __launch_bounds__(256) void rope_l2_split_kernel(
    const float* __restrict__ in, __nv_bfloat16* __restrict__ outh, __nv_bfloat16* __restrict__ outl,
    int nheads, const float* __restrict__ cosb, const float* __restrict__ sinb, float scale)
{
    int wid  = (blockIdx.x * 256 + threadIdx.x) >> 5;
    int lane = threadIdx.x & 31;
    int s  = wid / nheads;
    int hh = wid % nheads;
    size_t base = (size_t)s * nheads * HDIM + hh * HDIM + lane * 4;
    float4 vv = *(const float4*)(in + base);

    float c0 = cosb[s * 64 + lane * 2],     s0 = sinb[s * 64 + lane * 2];
    float c1 = cosb[s * 64 + lane * 2 + 1], s1 = sinb[s * 64 + lane * 2 + 1];
    float o0 = vv.x * c0 - vv.y * s0;
    float o1 = vv.x * s0 + vv.y * c0;
    float o2 = vv.z * c1 - vv.w * s1;
    float o3 = vv.z * s1 + vv.w * c1;

    float ss = o0*o0 + o1*o1 + o2*o2 + o3*o3;
#pragma unroll
    for (int o = 16; o; o >>= 1) ss += __shfl_xor_sync(0xffffffffu, ss, o);
    float rr = rsqrtf(ss * (1.f / HDIM) + 1e-5f) * scale;
    o0 *= rr; o1 *= rr; o2 *= rr; o3 *= rr;

    uint2 hv, lv;
    split2(o0, o1, hv.x, lv.x);
    split2(o2, o3, hv.y, lv.y);
    *(uint2*)(outh + base) = hv;
    *(uint2*)(outl + base) = lv;
}

// ================= transpose + bf16 hi/lo split: in[K,N] fp32 -> hi/lo [N,K] bf16 =================
// 64x64 tiles; output stores are paired along K (uint32 writes).
__global__ __launch_bounds__(256) void transpose_split_kernel(
    const float* __restrict__ in, __nv_bfloat16* __restrict__ hi, __nv_bfloat16* __restrict__ lo,
    int K, int N)
{
    __shared__ float s[64][65];
    int r0 = blockIdx.y * 64, c0 = blockIdx.x * 64;
#pragma unroll
    for (int i = 0; i < 8; i++) {
        int idx = threadIdx.x + i * 256;        // 2048 float2 units
        int lr = idx >> 5, p = idx & 31;
        float2 v = *(const float2*)(in + (size_t)(r0 + lr) * N + c0 + 2 * p);
        s[lr][2 * p]     = v.x;
        s[lr][2 * p + 1] = v.y;
    }
    __syncthreads();
#pragma unroll
    for (int i = 0; i < 8; i++) {
        int idx = threadIdx.x + i * 256;
        int lr = idx >> 5, p = idx & 31;        // out row = c0+lr, K pair = r0+2p
        float a = s[2 * p][lr];
        float b = s[2 * p + 1][lr];
        uint32_t hv, lv;
        split2(a, b, hv, lv);
        size_t o = (size_t)(c0 + lr) * K + (r0 + 2 * p);
        *(uint32_t*)(hi + o) = hv;
        *(uint32_t*)(lo + o) = lv;
    }
}

// ================= HMMA split-bf16 GEMM =================
// C[M,N] = A[M,K] @ B^T[N,K] (3-term hi/lo).
// Grid: (M/128, N/128) with M-block FASTEST (B-panel L2 reuse within a wave).
// Epilogue modes: fp32 C (+addend), bf16 hi/lo out, silu(gateMul)*acc fused.
#define TCG_STAGE_BYTES 65536
#define TCG_NSTAGE 3
#define TCG_SMEM (TCG_NSTAGE * TCG_STAGE_BYTES)

__global__ __launch_bounds__(256, 1) void tc_gemm_kernel(
    const __nv_bfloat16* __restrict__ Ahi, const __nv_bfloat16* __restrict__ Alo,
    const __nv_bfloat16* __restrict__ Bhi, const __nv_bfloat16* __restrict__ Blo,
    float* __restrict__ C, const float* __restrict__ addend,
    __nv_bfloat16* __restrict__ outHi, __nv_bfloat16* __restrict__ outLo,
    const float* __restrict__ gateMul,
    int M, int N, int K)
{
    extern __shared__ char sm[];
    uint32_t sbase = smem_u32(sm);
    int tid = threadIdx.x, lane = tid & 31, wid = tid >> 5;
    int warp_m = wid & 1, warp_n = wid >> 1;
    int by = blockIdx.x, bx = blockIdx.y;   // M-block fastest

    const __nv_bfloat16* srcA[2] = { Ahi + (size_t)(by * 128) * K, Alo + (size_t)(by * 128) * K };
    const __nv_bfloat16* srcB[2] = { Bhi + (size_t)(bx * 128) * K, Blo + (size_t)(bx * 128) * K };

    int nchunk = K >> 6;
    int ldrow = tid >> 3;
    int ldc16 = tid & 7;

    auto load_stage = [&](int stg, int c) {
        uint32_t dst0 = sbase + stg * TCG_STAGE_BYTES;
        int kc = c << 6;
#pragma unroll
        for (int hl = 0; hl < 2; hl++) {
            const __nv_bfloat16* sa = srcA[hl] + kc;
            const __nv_bfloat16* sb = srcB[hl] + kc;
            uint32_t da = dst0 + hl * 16384;
            uint32_t db = dst0 + 32768 + hl * 16384;
#pragma unroll
            for (int i = 0; i < 4; i++) {
                int row = ldrow + i * 32;
                uint32_t sw = row * 128 + ((ldc16 ^ (row & 7)) << 4);
                cp_async16(da + sw, sa + (size_t)row * K + ldc16 * 8);
                cp_async16(db + sw, sb + (size_t)row * K + ldc16 * 8);
            }
        }
    };

    load_stage(0, 0); CP_COMMIT();
    load_stage(1, 1); CP_COMMIT();

    float acc[4][4][4];
#pragma unroll
    for (int a = 0; a < 4; a++)
#pragma unroll
        for (int b = 0; b < 4; b++)
#pragma unroll
            for (int f = 0; f < 4; f++) acc[a][b][f] = 0.f;

    int a_r   = warp_m * 64 + (lane & 15);
    int a_kh  = lane >> 4;
    int b_r   = warp_n * 32 + (lane & 7) + ((lane >> 4) << 3);
    int b_kh  = (lane >> 3) & 1;

    for (int c = 0; c < nchunk; c++) {
        CP_WAIT1();
        __syncthreads();
        if (c + 2 < nchunk) load_stage((c + 2) % TCG_NSTAGE, c + 2);
        CP_COMMIT();

        uint32_t st = sbase + (c % TCG_NSTAGE) * TCG_STAGE_BYTES;
#pragma unroll
        for (int kk = 0; kk < 4; kk++) {
            int c16 = kk * 2;
            uint32_t ah[4][4], al[4][4], bh[2][4], bl[2][4];
#pragma unroll
            for (int mb = 0; mb < 4; mb++) {
                int r = a_r + mb * 16;
                uint32_t off = r * 128 + (((c16 + a_kh) ^ (r & 7)) << 4);
                ldsm4(ah[mb], st + off);
                ldsm4(al[mb], st + 16384 + off);
            }
#pragma unroll
            for (int nb = 0; nb < 2; nb++) {
                int r = b_r + nb * 16;
                uint32_t off = r * 128 + (((c16 + b_kh) ^ (r & 7)) << 4);
                ldsm4(bh[nb], st + 32768 + off);
                ldsm4(bl[nb], st + 49152 + off);
            }
#pragma unroll
            for (int mb = 0; mb < 4; mb++)
#pragma unroll
                for (int nb = 0; nb < 4; nb++) {
                    uint32_t b0h = bh[nb >> 1][(nb & 1) * 2], b1h = bh[nb >> 1][(nb & 1) * 2 + 1];
                    uint32_t b0l = bl[nb >> 1][(nb & 1) * 2], b1l = bl[nb >> 1][(nb & 1) * 2 + 1];
                    mma16816(acc[mb][nb], ah[mb], b0h, b1h);
                    mma16816(acc[mb][nb], ah[mb], b0l, b1l);
                    mma16816(acc[mb][nb], al[mb], b0h, b1h);
                }
        }
        __syncthreads();
    }

#pragma unroll
    for (int mb = 0; mb < 4; mb++) {
        int mrow = by * 128 + warp_m * 64 + mb * 16 + (lane >> 2);
#pragma unroll
        for (int nb = 0; nb < 4; nb++) {
            int ncol = bx * 128 + warp_n * 32 + nb * 8 + (lane & 3) * 2;
            size_t i0 = (size_t)mrow * N + ncol;
            size_t i1 = (size_t)(mrow + 8) * N + ncol;
            float2 r0 = make_float2(acc[mb][nb][0], acc[mb][nb][1]);
            float2 r1 = make_float2(acc[mb][nb][2], acc[mb][nb][3]);
            if (addend) {
                float2 a0 = *(const float2*)(addend + i0);
                float2 a1 = *(const float2*)(addend + i1);
                r0.x += a0.x; r0.y += a0.y;
                r1.x += a1.x; r1.y += a1.y;
            }
            if (gateMul) {
                float2 g0 = *(const float2*)(gateMul + i0);
                float2 g1 = *(const float2*)(gateMul + i1);
                r0.x *= g0.x / (1.f + __expf(-g0.x));
                r0.y *= g0.y / (1.f + __expf(-g0.y));
                r1.x *= g1.x / (1.f + __expf(-g1.x));
                r1.y *= g1.y / (1.f + __expf(-g1.y));
            }
            if (C) {
                *(float2*)(C + i0) = r0;
                *(float2*)(C + i1) = r1;
            }
            if (outHi) {
                uint32_t h0, l0, h1, l1;
                split2(r0.x, r0.y, h0, l0);
                split2(r1.x, r1.y, h1, l1);
                *(uint32_t*)(outHi + i0) = h0;
                *(uint32_t*)(outLo + i0) = l0;
                *(uint32_t*)(outHi + i1) = h1;
                *(uint32_t*)(outLo + i1) = l1;
            }
        }
    }
}

// ================= HMMA causal flash attention, GQA, split-bf16 =================
#define FA_STAGE_OFF 32768
#define FA_STAGE_BYTES 65536
#define FA_SMEM (FA_STAGE_OFF + 2 * FA_STAGE_BYTES)   // 160KB

__global__ __launch_bounds__(128, 1) void flash_attn_kernel(
    const __nv_bfloat16* __restrict__ qh, const __nv_bfloat16* __restrict__ ql,
    const __nv_bfloat16* __restrict__ kh, const __nv_bfloat16* __restrict__ kl,
    const __nv_bfloat16* __restrict__ vh, const __nv_bfloat16* __restrict__ vl,
    __nv_bfloat16* __restrict__ oh, __nv_bfloat16* __restrict__ ol)
{
    extern __shared__ char sm[];
    uint32_t sbase = smem_u32(sm);
    int qb = blockIdx.x, h = blockIdx.y, kvh = h >> 2;
    int tid = threadIdx.x, lane = tid & 31, w = tid >> 5;

#pragma unroll
    for (int i = 0; i < 8; i++) {
        int u = tid + i * 128;
        int row = u >> 4, c16 = u & 15;
        uint32_t dst = sbase + row * 256 + ((c16 ^ (row & 7)) << 4);
        size_t srco = (size_t)(qb * 64 + row) * DMODEL + h * HDIM + c16 * 8;
        cp_async16(dst,         qh + srco);
        cp_async16(dst + 16384, ql + srco);
    }

    auto load_kv = [&](int stg, int kb) {
        uint32_t dst0 = sbase + FA_STAGE_OFF + stg * FA_STAGE_BYTES;
        const __nv_bfloat16* srcs[4] = { kh, kl, vh, vl };
#pragma unroll
        for (int b = 0; b < 4; b++) {
            const __nv_bfloat16* s = srcs[b];
#pragma unroll
            for (int i = 0; i < 8; i++) {
                int u = tid + i * 128;
                int row = u >> 4, c16 = u & 15;
                uint32_t dst = dst0 + b * 16384 + row * 256 + ((c16 ^ (row & 7)) << 4);
                cp_async16(dst, s + (size_t)(kb * 64 + row) * (NKVH * HDIM) + kvh * HDIM + c16 * 8);
            }
        }
    };

    load_kv(0, 0); CP_COMMIT();
    if (qb >= 1) load_kv(1, 1);
    CP_COMMIT();

    float O[16][4];
#pragma unroll
    for (int i = 0; i < 16; i++)
#pragma unroll
        for (int f = 0; f < 4; f++) O[i][f] = 0.f;
    float m_lo = -1e30f, m_hi = -1e30f, l_lo = 0.f, l_hi = 0.f;

    int r_loc = w * 16 + (lane >> 2);

    for (int kb = 0; kb <= qb; kb++) {
        CP_WAIT1();
        __syncthreads();
        uint32_t kbase = sbase + FA_STAGE_OFF + (kb & 1) * FA_STAGE_BYTES;

        float S[8][4];
#pragma unroll
        for (int i = 0; i < 8; i++)
#pragma unroll
            for (int f = 0; f < 4; f++) S[i][f] = 0.f;

#pragma unroll
        for (int kk = 0; kk < 8; kk++) {
            uint32_t aqh[4], aql[4];
            int ar = w * 16 + (lane & 15);
            int ac = kk * 2 + (lane >> 4);
            uint32_t aoff = ar * 256 + ((ac ^ (ar & 7)) << 4);
            ldsm4(aqh, sbase + aoff);
            ldsm4(aql, sbase + 16384 + aoff);
#pragma unroll
            for (int nblk = 0; nblk < 4; nblk++) {
                int br = nblk * 16 + (lane & 7) + ((lane >> 4) << 3);
                int bc = kk * 2 + ((lane >> 3) & 1);
                uint32_t boff = br * 256 + ((bc ^ (br & 7)) << 4);
                uint32_t bh4[4], bl4[4];
                ldsm4(bh4, kbase + boff);
                ldsm4(bl4, kbase + 16384 + boff);
                mma16816(S[2*nblk],   aqh, bh4[0], bh4[1]);
                mma16816(S[2*nblk],   aqh, bl4[0], bl4[1]);
                mma16816(S[2*nblk],   aql, bh4[0], bh4[1]);
                mma16816(S[2*nblk+1], aqh, bh4[2], bh4[3]);
                mma16816(S[2*nblk+1], aqh, bl4[2], bl4[3]);
                mma16816(S[2*nblk+1], aql, bh4[2], bh4[3]);
            }
        }

        if (kb == qb) {
#pragma unroll
            for (int nt = 0; nt < 8; nt++) {
                int c = nt * 8 + (lane & 3) * 2;
                if (c     > r_loc)     S[nt][0] = -1e30f;
                if (c + 1 > r_loc)     S[nt][1] = -1e30f;
                if (c     > r_loc + 8) S[nt][2] = -1e30f;
                if (c + 1 > r_loc + 8) S[nt][3] = -1e30f;
            }
        }

        float rm_lo = -1e30f, rm_hi = -1e30f;
#pragma unroll
        for (int nt = 0; nt < 8; nt++) {
            rm_lo = fmaxf(rm_lo, fmaxf(S[nt][0], S[nt][1]));
            rm_hi = fmaxf(rm_hi, fmaxf(S[nt][2], S[nt][3]));
        }
        rm_lo = fmaxf(rm_lo, __shfl_xor_sync(0xffffffffu, rm_lo, 1));
        rm_lo = fmaxf(rm_lo, __shfl_xor_sync(0xffffffffu, rm_lo, 2));
        rm_hi = fmaxf(rm_hi, __shfl_xor_sync(0xffffffffu, rm_hi, 1));
        rm_hi = fmaxf(rm_hi, __shfl_xor_sync(0xffffffffu, rm_hi, 2));
        float mn_lo = fmaxf(m_lo, rm_lo), mn_hi = fmaxf(m_hi, rm_hi);
        float corr_lo = __expf(m_lo - mn_lo), corr_hi = __expf(m_hi - mn_hi);

        uint32_t ph[8][2], pl[8][2];
        float sum_lo = 0.f, sum_hi = 0.f;
#pragma unroll
        for (int nt = 0; nt < 8; nt++) {
            float p0 = __expf(S[nt][0] - mn_lo);
            float p1 = __expf(S[nt][1] - mn_lo);
            float p2 = __expf(S[nt][2] - mn_hi);
            float p3 = __expf(S[nt][3] - mn_hi);
            sum_lo += p0 + p1; sum_hi += p2 + p3;
            split2(p0, p1, ph[nt][0], pl[nt][0]);
            split2(p2, p3, ph[nt][1], pl[nt][1]);
        }
        sum_lo += __shfl_xor_sync(0xffffffffu, sum_lo, 1);
        sum_lo += __shfl_xor_sync(0xffffffffu, sum_lo, 2);
        sum_hi += __shfl_xor_sync(0xffffffffu, sum_hi, 1);
        sum_hi += __shfl_xor_sync(0xffffffffu, sum_hi, 2);
        l_lo = l_lo * corr_lo + sum_lo;
        l_hi = l_hi * corr_hi + sum_hi;
        m_lo = mn_lo; m_hi = mn_hi;
#pragma unroll
        for (int ot = 0; ot < 16; ot++) {
            O[ot][0] *= corr_lo; O[ot][1] *= corr_lo;
            O[ot][2] *= corr_hi; O[ot][3] *= corr_hi;
        }

        uint32_t vbase = kbase + 32768;
#pragma unroll
        for (int kt = 0; kt < 4; kt++) {
            uint32_t aH[4] = { ph[2*kt][0], ph[2*kt][1], ph[2*kt+1][0], ph[2*kt+1][1] };
            uint32_t aL[4] = { pl[2*kt][0], pl[2*kt][1], pl[2*kt+1][0], pl[2*kt+1][1] };
            int krow = kt * 16 + (lane & 7) + ((lane >> 3) & 1) * 8;
#pragma unroll
            for (int ob = 0; ob < 8; ob++) {
                int cu = ob * 2 + (lane >> 4);
                uint32_t off = krow * 256 + ((cu ^ (krow & 7)) << 4);
                uint32_t bvh[4], bvl[4];
                ldsm4t(bvh, vbase + off);
                ldsm4t(bvl, vbase + 16384 + off);
                mma16816(O[2*ob],   aH, bvh[0], bvh[1]);
                mma16816(O[2*ob],   aH, bvl[0], bvl[1]);
                mma16816(O[2*ob],   aL, bvh[0], bvh[1]);
                mma16816(O[2*ob+1], aH, bvh[2], bvh[3]);
                mma16816(O[2*ob+1], aH, bvl[2], bvl[3]);
                mma16816(O[2*ob+1], aL, bvh[2], bvh[3]);
            }
        }

        __syncthreads();
        if (kb + 2 <= qb) load_kv(kb & 1, kb + 2);
        CP_COMMIT();
    }

    float il_lo = 1.f / l_lo, il_hi = 1.f / l_hi;
    int row0 = qb * 64 + r_loc;
#pragma unroll
    for (int ot = 0; ot < 16; ot++) {
        int col = h * HDIM + ot * 8 + (lane & 3) * 2;
        float o0 = O[ot][0] * il_lo, o1 = O[ot][1] * il_lo;
        float o2 = O[ot][2] * il_hi, o3 = O[ot][3] * il_hi;
        uint32_t h0, l0, h1, l1;
        split2(o0, o1, h0, l0);
        split2(o2, o3, h1, l1);
        size_t i0 = (size_t)row0 * DMODEL + col;
        size_t i1 = (size_t)(row0 + 8) * DMODEL + col;
        *(uint32_t*)(oh + i0) = h0;
        *(uint32_t*)(ol + i0) = l0;
        *(uint32_t*)(oh + i1) = h1;
        *(uint32_t*)(ol + i1) = l1;
    }
}

// ================= host launcher =================
extern "C" void kernel_launch(void* const* d_in, const int* in_sizes, int n_in,
                              void* d_out, int out_size)
{
    const float* hidden = (const float*)d_in[0];
    const float* cosb  = (const float*)d_in[2];
    const float* sinb  = (const float*)d_in[3];
    const float* ln1   = (const float*)d_in[4];
    const float* wq    = (const float*)d_in[5];
    const float* wk    = (const float*)d_in[6];
    const float* wv    = (const float*)d_in[7];
    const float* wo    = (const float*)d_in[8];
    const float* ln2   = (const float*)d_in[9];
    const float* gatew = (const float*)d_in[10];
    const float* upw   = (const float*)d_in[11];
    const float* downw = (const float*)d_in[12];
    float* out = (float*)d_out;

    float *q, *k, *h, *gate;
    cudaGetSymbolAddress((void**)&q,    g_q);
    cudaGetSymbolAddress((void**)&k,    g_k);
    cudaGetSymbolAddress((void**)&h,    g_h);
    cudaGetSymbolAddress((void**)&gate, g_gate);

    __nv_bfloat16 *wqTh,*wqTl,*wkTh,*wkTl,*wvTh,*wvTl,*woTh,*woTl,*gwTh,*gwTl,*uwTh,*uwTl,*dwTh,*dwTl;
    cudaGetSymbolAddress((void**)&wqTh, g_wqT_h); cudaGetSymbolAddress((void**)&wqTl, g_wqT_l);
    cudaGetSymbolAddress((void**)&wkTh, g_wkT_h); cudaGetSymbolAddress((void**)&wkTl, g_wkT_l);
    cudaGetSymbolAddress((void**)&wvTh, g_wvT_h); cudaGetSymbolAddress((void**)&wvTl, g_wvT_l);
    cudaGetSymbolAddress((void**)&woTh, g_woT_h); cudaGetSymbolAddress((void**)&woTl, g_woT_l);
    cudaGetSymbolAddress((void**)&gwTh, g_gwT_h); cudaGetSymbolAddress((void**)&gwTl, g_gwT_l);
    cudaGetSymbolAddress((void**)&uwTh, g_uwT_h); cudaGetSymbolAddress((void**)&uwTl, g_uwT_l);
    cudaGetSymbolAddress((void**)&dwTh, g_dwT_h); cudaGetSymbolAddress((void**)&dwTl, g_dwT_l);

    __nv_bfloat16 *xnh,*xnl,*qhp,*qlp,*khp,*klp,*vhp,*vlp,*ath,*atl,*x2h,*x2l,*gah,*gal;
    cudaGetSymbolAddress((void**)&xnh, g_xn_h); cudaGetSymbolAddress((void**)&xnl, g_xn_l);
    cudaGetSymbolAddress((void**)&qhp, g_qh);   cudaGetSymbolAddress((void**)&qlp, g_ql);
    cudaGetSymbolAddress((void**)&khp, g_kh);   cudaGetSymbolAddress((void**)&klp, g_kl);
    cudaGetSymbolAddress((void**)&vhp, g_vh);   cudaGetSymbolAddress((void**)&vlp, g_vl);
    cudaGetSymbolAddress((void**)&ath, g_at_h); cudaGetSymbolAddress((void**)&atl, g_at_l);
    cudaGetSymbolAddress((void**)&x2h, g_x2_h); cudaGetSymbolAddress((void**)&x2l, g_x2_l);
    cudaGetSymbolAddress((void**)&gah, g_ga_h); cudaGetSymbolAddress((void**)&gal, g_ga_l);

    cudaFuncSetAttribute(tc_gemm_kernel, cudaFuncAttributeMaxDynamicSharedMemorySize, TCG_SMEM);
    cudaFuncSetAttribute(flash_attn_kernel, cudaFuncAttributeMaxDynamicSharedMemorySize, FA_SMEM);

    // ---- weight transposes + hi/lo splits ----
    transpose_split_kernel<<<dim3(DMODEL/64, DMODEL/64), 256>>>(wq, wqTh, wqTl, DMODEL, DMODEL);
    transpose_split_kernel<<<dim3(NKVH*HDIM/64, DMODEL/64), 256>>>(wk, wkTh, wkTl, DMODEL, NKVH*HDIM);
    transpose_split_kernel<<<dim3(NKVH*HDIM/64, DMODEL/64), 256>>>(wv, wvTh, wvTl, DMODEL, NKVH*HDIM);
    transpose_split_kernel<<<dim3(DMODEL/64, DMODEL/64), 256>>>(wo, woTh, woTl, DMODEL, DMODEL);
    transpose_split_kernel<<<dim3(DFFN/64, DMODEL/64), 256>>>(gatew, gwTh, gwTl, DMODEL, DFFN);
    transpose_split_kernel<<<dim3(DFFN/64, DMODEL/64), 256>>>(upw,   uwTh, uwTl, DMODEL, DFFN);
    transpose_split_kernel<<<dim3(DMODEL/64, DFFN/64), 256>>>(downw, dwTh, dwTl, DFFN, DMODEL);

    // 1) x = rmsnorm(hidden, ln1) -> bf16 hi/lo
    rmsnorm_split_kernel<<<S_LEN, 256>>>(hidden, ln1, xnh, xnl);

    // 2) q/k fp32 (for rope); v -> bf16 hi/lo directly  [grid: M-fastest]
    tc_gemm_kernel<<<dim3(S_LEN/128, DMODEL/128), 256, TCG_SMEM>>>(xnh, xnl, wqTh, wqTl, q, nullptr, nullptr, nullptr, nullptr, S_LEN, DMODEL, DMODEL);
    tc_gemm_kernel<<<dim3(S_LEN/128, NKVH*HDIM/128), 256, TCG_SMEM>>>(xnh, xnl, wkTh, wkTl, k, nullptr, nullptr, nullptr, nullptr, S_LEN, NKVH*HDIM, DMODEL);
    tc_gemm_kernel<<<dim3(S_LEN/128, NKVH*HDIM/128), 256, TCG_SMEM>>>(xnh, xnl, wvTh, wvTl, nullptr, nullptr, vhp, vlp, nullptr, S_LEN, NKVH*HDIM, DMODEL);

    // 3) RoPE + L2-norm -> bf16 hi/lo; fold HD^-0.5 into q
    const float qscale = 0.08838834764831845f;
    rope_l2_split_kernel<<<S_LEN * NHEADS / 8, 256>>>(q, qhp, qlp, NHEADS, cosb, sinb, qscale);
    rope_l2_split_kernel<<<S_LEN * NKVH  / 8, 256>>>(k, khp, klp, NKVH,  cosb, sinb, 1.f);

    // 4) HMMA causal flash attention -> attn bf16 hi/lo
    flash_attn_kernel<<<dim3(S_LEN / 64, NHEADS), 128, FA_SMEM>>>(qhp, qlp, khp, klp, vhp, vlp, ath, atl);

    // 5) h = hidden + attn @ wo (fp32)
    tc_gemm_kernel<<<dim3(S_LEN/128, DMODEL/128), 256, TCG_SMEM>>>(ath, atl, woTh, woTl, h, hidden, nullptr, nullptr, nullptr, S_LEN, DMODEL, DMODEL);

    // 6) x2 = rmsnorm(h, ln2) -> bf16 hi/lo
    rmsnorm_split_kernel<<<S_LEN, 256>>>(h, ln2, x2h, x2l);

    // 7) FFN: gate fp32; up with fused silu(gate)*up -> bf16 hi/lo
    tc_gemm_kernel<<<dim3(S_LEN/128, DFFN/128), 256, TCG_SMEM>>>(x2h, x2l, gwTh, gwTl, gate, nullptr, nullptr, nullptr, nullptr, S_LEN, DFFN, DMODEL);
    tc_gemm_kernel<<<dim3(S_LEN/128, DFFN/128), 256, TCG_SMEM>>>(x2h, x2l, uwTh, uwTl, nullptr, nullptr, gah, gal, gate, S_LEN, DFFN, DMODEL);

    // 8) out = h + act @ down
    tc_gemm_kernel<<<dim3(S_LEN/128, DMODEL/128), 256, TCG_SMEM>>>(gah, gal, dwTh, dwTl, out, h, nullptr, nullptr, nullptr, S_LEN, DMODEL, DFFN);
}